// round 5
// baseline (speedup 1.0000x reference)
#include <cuda_runtime.h>
#include <math.h>
#include <stdint.h>

// Problem shape (fixed by dataset): B=512, O=1024, I=512
#define I_DIM 512
#define B_MAX 512
#define O_MAX 1024

// Scratch (allocation-free rule: __device__ globals)
__device__ __align__(16) float g_xt[I_DIM * B_MAX];   // x transposed  [i][b]
__device__ __align__(16) float g_v [I_DIM * O_MAX];   // [i][o]
__device__ __align__(16) float g_nt[I_DIM * O_MAX];
__device__ __align__(16) float g_wk[I_DIM * O_MAX];
__device__ __align__(16) float g_w [I_DIM * O_MAX];

// constants
// C  = sqrt(0.5*log2(e)) ; u = s*C  =>  2^(-u^2) = exp(-0.5 s^2)
// K  = 1/C^2 = 2*ln2     ; 1 - s^2 = 1 + nu2*K  (nu2 = -u^2)
#define CC 0.84932184f
#define KK 1.3862944f

// ---------------- prologue: param transform + transpose ----------------
__global__ void prep_params(const float* __restrict__ t,
                            const float* __restrict__ sraw,
                            const float* __restrict__ w,
                            int O, int I) {
    int o = blockIdx.x * blockDim.x + threadIdx.x;   // coalesced writes over o
    int i = blockIdx.y;
    if (o >= O) return;
    size_t gi = (size_t)o * I + i;                   // strided reads (L2-hot)
    float tr = t[gi];
    float sr = sraw[gi];
    float wv = w[gi];
    float scale = 0.001f + log1pf(expf(sr));         // A_MIN + softplus
    float v = CC / (scale + 1e-8f);
    size_t oi = (size_t)i * O + o;
    g_v [oi] = v;
    g_nt[oi] = -tr * v;
    g_wk[oi] = wv * KK;
    g_w [oi] = wv;
}

__global__ void prep_x(const float* __restrict__ x, int B, int I) {
    int b = blockIdx.x * blockDim.x + threadIdx.x;
    int i = blockIdx.y;
    if (b >= B) return;
    g_xt[(size_t)i * B + b] = x[(size_t)b * I + i];
}

// ---------------- main kernel ----------------
// Block tile: 64 (b) x 64 (o), 256 threads, 4x4 register micro-tile.
// Smem: transposed chunks [IC][64] for x and the 4 param streams, double-buffered.
#define BT 64
#define OT 64
#define ICK 64
#define BUF_FLOATS (ICK * (BT + 4 * OT))   // 20480 floats = 80KB per buffer

__global__ __launch_bounds__(256, 1)
void wavelet_main(float* __restrict__ out, int B, int O, int I) {
    extern __shared__ float sm[];

    const int tid = threadIdx.x;
    const int tx  = tid & 15;          // o lane
    const int ty  = tid >> 4;          // b lane
    const int b0  = blockIdx.x * BT;
    const int o0  = blockIdx.y * OT;

    float acc[4][4];
#pragma unroll
    for (int bb = 0; bb < 4; bb++)
#pragma unroll
        for (int oo = 0; oo < 4; oo++) acc[bb][oo] = 0.0f;

    // chunk loader: coalesced float4 global reads, conflict-free float4 STS
    auto load_chunk = [&](int ic, int buf) {
        float4* s4 = reinterpret_cast<float4*>(sm + buf * BUF_FLOATS);
        // x tile: ICK rows x BT cols  -> 1024 float4, 4 per thread
#pragma unroll
        for (int q = 0; q < 4; q++) {
            int p   = tid + q * 256;
            int row = p >> 4;          // BT/4 == 16
            int c   = p & 15;
            s4[p] = *(reinterpret_cast<const float4*>(g_xt + (size_t)(ic + row) * B + b0) + c);
        }
        float4* sp = s4 + (ICK * BT) / 4;
        const float* __restrict__ srcs[4] = { g_v, g_nt, g_wk, g_w };
#pragma unroll
        for (int a = 0; a < 4; a++) {
#pragma unroll
            for (int q = 0; q < 4; q++) {
                int p   = tid + q * 256;
                int row = p >> 4;      // OT/4 == 16
                int c   = p & 15;
                sp[a * (ICK * OT) / 4 + p] =
                    *(reinterpret_cast<const float4*>(srcs[a] + (size_t)(ic + row) * O + o0) + c);
            }
        }
    };

    load_chunk(0, 0);
    __syncthreads();

    const int nchunks = I / ICK;       // 8
    for (int k = 0; k < nchunks; k++) {
        // prefetch next chunk into the other buffer (LDG latency hidden by compute)
        if (k + 1 < nchunks) load_chunk((k + 1) * ICK, (k + 1) & 1);

        const float* s   = sm + (k & 1) * BUF_FLOATS;
        const float* xs  = s;
        const float* vs  = s + ICK * BT;
        const float* nts = vs + ICK * OT;
        const float* wks = nts + ICK * OT;
        const float* ws  = wks + ICK * OT;

#pragma unroll 4
        for (int i = 0; i < ICK; i++) {
            float xr[4], vr[4], ntr[4], wkr[4], wr[4];
#pragma unroll
            for (int r = 0; r < 4; r++) {
                xr [r] = xs [i * BT + ty + 16 * r];
                vr [r] = vs [i * OT + tx + 16 * r];
                ntr[r] = nts[i * OT + tx + 16 * r];
                wkr[r] = wks[i * OT + tx + 16 * r];
                wr [r] = ws [i * OT + tx + 16 * r];
            }
#pragma unroll
            for (int bb = 0; bb < 4; bb++) {
#pragma unroll
                for (int oo = 0; oo < 4; oo++) {
                    float u   = fmaf(xr[bb], vr[oo], ntr[oo]);   // s * C
                    float nu2 = u * (-u);                        // -u^2
                    float ex;
                    asm("ex2.approx.ftz.f32 %0, %1;" : "=f"(ex) : "f"(nu2));
                    float h   = fmaf(nu2, wkr[oo], wr[oo]);      // w*(1 - s^2)
                    acc[bb][oo] = fmaf(h, ex, acc[bb][oo]);
                }
            }
        }
        __syncthreads();
    }

    // epilogue: write 4x4 micro-tile
#pragma unroll
    for (int bb = 0; bb < 4; bb++) {
        int b = b0 + ty + 16 * bb;
#pragma unroll
        for (int oo = 0; oo < 4; oo++) {
            out[(size_t)b * O + o0 + tx + 16 * oo] = acc[bb][oo];
        }
    }
}

// ---------------- launch ----------------
extern "C" void kernel_launch(void* const* d_in, const int* in_sizes, int n_in,
                              void* d_out, int out_size) {
    const float* x    = (const float*)d_in[0];
    const float* t    = (const float*)d_in[1];
    const float* sraw = (const float*)d_in[2];
    const float* w    = (const float*)d_in[3];
    float* out = (float*)d_out;

    const int I = I_DIM;
    const int B = in_sizes[0] / I;   // 512
    const int O = in_sizes[1] / I;   // 1024

    // prologue (cheap: ~0.5M elems each)
    prep_params<<<dim3((O + 255) / 256, I), 256>>>(t, sraw, w, O, I);
    prep_x<<<dim3((B + 255) / 256, I), 256>>>(x, B, I);

    // main kernel: 2 x 80KB dynamic smem
    int smem_bytes = 2 * BUF_FLOATS * (int)sizeof(float);
    cudaFuncSetAttribute(wavelet_main, cudaFuncAttributeMaxDynamicSharedMemorySize, smem_bytes);
    wavelet_main<<<dim3(B / BT, O / OT), 256, smem_bytes>>>(out, B, O, I);
}